// round 9
// baseline (speedup 1.0000x reference)
#include <cuda_runtime.h>
#include <cstdint>

#define BB 8
#define EE 2048
#define NN 2048
#define FF 128

// Y scratch: [b][n][c'] tf32 bit patterns, columns permuted within each 32-block:
// c' = (c & ~31) | ((c & 7) << 2) | ((c >> 3) & 3)   (8 MiB)
__device__ float g_Y[BB * NN * FF];

// ---------------- helpers ----------------
__device__ __forceinline__ uint32_t smem_u32(const void* p) {
    uint32_t a;
    asm("{ .reg .u64 t; cvta.to.shared.u64 t, %1; cvt.u32.u64 %0, t; }"
        : "=r"(a) : "l"(p));
    return a;
}
__device__ __forceinline__ uint32_t f2tf32(float x) {
    uint32_t r;
    asm("cvt.rna.tf32.f32 %0, %1;" : "=r"(r) : "f"(x));
    return r;
}
__device__ __forceinline__ void mma_tf32(float d[4], const uint32_t a[4],
                                         const uint32_t b[2], const float c[4]) {
    asm volatile(
        "mma.sync.aligned.m16n8k8.row.col.f32.tf32.tf32.f32 "
        "{%0,%1,%2,%3}, {%4,%5,%6,%7}, {%8,%9}, {%10,%11,%12,%13};"
        : "=f"(d[0]), "=f"(d[1]), "=f"(d[2]), "=f"(d[3])
        : "r"(a[0]), "r"(a[1]), "r"(a[2]), "r"(a[3]),
          "r"(b[0]), "r"(b[1]),
          "f"(c[0]), "f"(c[1]), "f"(c[2]), "f"(c[3]));
}
__device__ __forceinline__ void cpa16(uint32_t s, const void* g) {
    asm volatile("cp.async.cg.shared.global [%0], [%1], 16;" :: "r"(s), "l"(g));
}
__device__ __forceinline__ void cpa_commit() { asm volatile("cp.async.commit_group;"); }
template <int W> __device__ __forceinline__ void cpa_wait() {
    asm volatile("cp.async.wait_group %0;" :: "n"(W));
}

#define MBAR_INIT(addr, cnt) \
    asm volatile("mbarrier.init.shared.b64 [%0], %1;" :: "r"((uint32_t)(addr)), "r"((uint32_t)(cnt)) : "memory")
#define MBAR_ARRIVE(addr) \
    asm volatile("mbarrier.arrive.shared.b64 _, [%0];" :: "r"((uint32_t)(addr)) : "memory")
#define MBAR_WAIT(addr, ph) do {                                                     \
    uint32_t _a = (uint32_t)(addr), _p = (uint32_t)(ph);                             \
    asm volatile("{\n\t.reg .pred P;\n\t"                                            \
        "WL%=:\n\t"                                                                  \
        "mbarrier.try_wait.parity.acquire.cta.shared::cta.b64 P, [%0], %1, 0x989680;\n\t" \
        "@P bra.uni WD%=;\n\t"                                                       \
        "bra.uni WL%=;\n\t"                                                          \
        "WD%=:\n\t}" :: "r"(_a), "r"(_p) : "memory");                                \
} while (0)
#define CP_MBAR_ARRIVE(addr) \
    asm volatile("cp.async.mbarrier.arrive.shared::cta.b64 [%0];" :: "r"((uint32_t)(addr)) : "memory")

// ---------------- Kernel A: Y = tf32(X @ W^T), permuted columns ----------------
#define A_SMEM_BYTES ((64 + 128) * 132 * 4)

__global__ __launch_bounds__(256, 2) void k_xw(const float* __restrict__ X,
                                               const float* __restrict__ W) {
    extern __shared__ float sm[];
    float* sX = sm;              // [64][132]
    float* sW = sm + 64 * 132;   // [128][132]
    const int tid = threadIdx.x;
    const long rbase = (long)blockIdx.x * 64;

    uint32_t sXb = (uint32_t)__cvta_generic_to_shared(sX);
    uint32_t sWb = (uint32_t)__cvta_generic_to_shared(sW);

#pragma unroll
    for (int i = 0; i < 8; ++i) {
        int id = tid + i * 256;
        int r = id >> 5;
        int c4 = (id & 31) * 4;
        cpa16(sXb + (uint32_t)(r * 132 + c4) * 4, X + (rbase + r) * FF + c4);
    }
#pragma unroll
    for (int i = 0; i < 16; ++i) {
        int id = tid + i * 256;
        int r = id >> 5;
        int c4 = (id & 31) * 4;
        cpa16(sWb + (uint32_t)(r * 132 + c4) * 4, W + r * FF + c4);
    }
    cpa_commit();
    cpa_wait<0>();
    __syncthreads();

    const int lane = tid & 31, warp = tid >> 5;
    const int wm = warp & 1, wn = warp >> 1;
    const int gid = lane >> 2, tig = lane & 3;

    float acc[2][4][4];
#pragma unroll
    for (int mt = 0; mt < 2; ++mt)
#pragma unroll
        for (int nt = 0; nt < 4; ++nt)
#pragma unroll
            for (int j = 0; j < 4; ++j) acc[mt][nt][j] = 0.f;

#pragma unroll
    for (int ks = 0; ks < 16; ++ks) {
        const int k0 = ks * 8;
        uint32_t af[2][4];
#pragma unroll
        for (int mt = 0; mt < 2; ++mt) {
            int r = wm * 32 + mt * 16 + gid;
            af[mt][0] = f2tf32(sX[r * 132 + k0 + tig]);
            af[mt][1] = f2tf32(sX[(r + 8) * 132 + k0 + tig]);
            af[mt][2] = f2tf32(sX[r * 132 + k0 + tig + 4]);
            af[mt][3] = f2tf32(sX[(r + 8) * 132 + k0 + tig + 4]);
        }
        uint32_t bf[4][2];
#pragma unroll
        for (int nt = 0; nt < 4; ++nt) {
            int f = wn * 32 + nt * 8 + gid;
            bf[nt][0] = f2tf32(sW[f * 132 + k0 + tig]);
            bf[nt][1] = f2tf32(sW[f * 132 + k0 + tig + 4]);
        }
#pragma unroll
        for (int mt = 0; mt < 2; ++mt)
#pragma unroll
            for (int nt = 0; nt < 4; ++nt)
                mma_tf32(acc[mt][nt], af[mt], bf[nt], acc[mt][nt]);
    }

    // permuted store via smem (reuse sX region: 64*128 floats)
    __syncthreads();
    uint32_t* sOut = (uint32_t*)sX;
#pragma unroll
    for (int mt = 0; mt < 2; ++mt)
#pragma unroll
        for (int h = 0; h < 2; ++h) {
            int r = wm * 32 + mt * 16 + gid + 8 * h;
#pragma unroll
            for (int nt = 0; nt < 4; ++nt) {
                // original cols c0 = wn*32 + nt*8 + 2*tig, c1 = c0+1
                int cp0 = wn * 32 + 8 * tig + nt;        // perm(c0)
                sOut[r * 128 + cp0] = f2tf32(acc[mt][nt][2 * h + 0]);
                sOut[r * 128 + cp0 + 4] = f2tf32(acc[mt][nt][2 * h + 1]);  // perm(c1)
            }
        }
    __syncthreads();
#pragma unroll
    for (int i = 0; i < 8; ++i) {
        int id = tid + i * 256;
        int row = id >> 5;
        int c4 = (id & 31) * 4;
        float4 q = *(float4*)&((float*)sOut)[row * 128 + c4];
        *(float4*)&g_Y[(rbase + row) * FF + c4] = q;
    }
}

// ---------------- Kernel B: warp-specialized pipelined masked GEMM ----------------
// 384 threads: warps 0-7 = MMA consumers (64 edges x 128 feats),
//              warps 8-11 = producers (adj LDG -> ballot -> EXPANDED tf32 A tile
//              in MMA-fragment order; Y via cp.async).
// 4-stage ring. Consumers: zero ALU in hot loop (LDS.128 + MMA only).
//
// Expanded A stage layout: [ks(4)][wm(2)][mt(2)][lane(32)] x float4
//   float4 = { bit(r0,p0), bit(r0+8,p0), bit(r0,p1), bit(r0+8,p1) } as tf32 1.0/0.0
//   r0 = wm*32+mt*16+(lane>>2), p0 = ks*8+(lane&3), p1 = p0+4.
#define STG_Y (32 * 136 * 4)                 // 17408 B
#define STG_A (4 * 2 * 2 * 32 * 16)          // 8192 B
#define OFF_Y 0
#define OFF_A (4 * STG_Y)                    // 69632
#define OFF_MASK (OFF_A + 4 * STG_A)         // 102400
#define OFF_FULL (OFF_MASK + 4 * 64 * 4)     // 103424
#define OFF_EMPTY (OFF_FULL + 32)            // 103456
#define B_SMEM_BYTES (OFF_EMPTY + 32)        // 103488

__global__ __launch_bounds__(384, 2) void k_agg(const float* __restrict__ adj,
                                                const float* __restrict__ bias,
                                                float* __restrict__ out) {
    extern __shared__ char smc[];
    const uint32_t sb = smem_u32(smc);
    const int tid = threadIdx.x, wid = tid >> 5, lane = tid & 31;
    const int eb = blockIdx.x * 64, b = blockIdx.y;
    const float* adjBase = adj + ((long)b * EE + eb) * NN;
    const float* Yb = g_Y + (long)b * NN * FF;

    if (tid == 0) {
#pragma unroll
        for (int i = 0; i < 4; ++i) {
            MBAR_INIT(sb + OFF_FULL + i * 8, 128);    // producers; cp.async arrivals self-balance
            MBAR_INIT(sb + OFF_EMPTY + i * 8, 256);   // consumer threads
        }
    }
    __syncthreads();

    if (wid >= 8) {
        // ===================== producer =====================
        const int p = tid - 256;            // 0..127
        const int pw = p >> 5, pl = p & 31;
        const float* arow = adjBase + (long)(pw * 16) * NN + pl;

        // expansion role: p -> (ewm, emt, elane)
        const int ewm = p >> 6, emt = (p >> 5) & 1, elane = p & 31;
        const int egid = elane >> 2, etig = elane & 3;
        const int er0 = ewm * 32 + emt * 16 + egid;      // row for .x/.z
        // mask words for rows er0 and er0+8 (within the 64-row tile)

        float v[16], vn[16];
#pragma unroll
        for (int i = 0; i < 16; ++i) v[i] = arow[(long)i * NN];   // chunk 0

#pragma unroll 1
        for (int s = 0; s < NN / 32; ++s) {
            const int slot = s & 3;
            MBAR_WAIT(sb + OFF_EMPTY + slot * 8, ((s >> 2) & 1) ^ 1);

            // Y tile via cp.async (16 KB / 128 threads = 8 x 16B each)
            const float* yp = Yb + (long)s * 32 * FF;
            uint32_t sy = sb + OFF_Y + slot * STG_Y;
#pragma unroll
            for (int i = 0; i < 8; ++i) {
                int cc = p + i * 128;
                int k = cc >> 5, c4 = (cc & 31) * 4;
                cpa16(sy + (uint32_t)(k * 136 + c4) * 4, yp + k * FF + c4);
            }
            CP_MBAR_ARRIVE(sb + OFF_FULL + slot * 8);

            // prefetch next adj chunk into regs (hide LDG latency)
            if (s + 1 < NN / 32) {
                const float* an = arow + (s + 1) * 32;
#pragma unroll
                for (int i = 0; i < 16; ++i) vn[i] = an[(long)i * NN];
            }

            // ballot rows into bitmasks
#pragma unroll
            for (int i = 0; i < 16; ++i) {
                uint32_t m = __ballot_sync(0xffffffffu, v[i] == -1.f);
                if (pl == i)
                    *(uint32_t*)(smc + OFF_MASK + (slot * 64 + pw * 16 + i) * 4) = m;
            }
            // make all 64 bitmask words visible to all 4 producer warps
            asm volatile("bar.sync 1, 128;" ::: "memory");

            // expand to tf32 A tile in fragment order
            {
                uint32_t m0 = *(const uint32_t*)(smc + OFF_MASK + (slot * 64 + er0) * 4);
                uint32_t m1 = *(const uint32_t*)(smc + OFF_MASK + (slot * 64 + er0 + 8) * 4);
                uint32_t abase = sb + OFF_A + slot * STG_A + (ewm * 2 + emt) * 512 + elane * 16;
#pragma unroll
                for (int ks = 0; ks < 4; ++ks) {
                    const int p0 = ks * 8 + etig, p1 = p0 + 4;
                    uint32_t fx = ((m0 >> p0) & 1u) * 0x3f800000u;
                    uint32_t fy = ((m1 >> p0) & 1u) * 0x3f800000u;
                    uint32_t fz = ((m0 >> p1) & 1u) * 0x3f800000u;
                    uint32_t fw = ((m1 >> p1) & 1u) * 0x3f800000u;
                    asm volatile("st.shared.v4.b32 [%0], {%1,%2,%3,%4};"
                                 :: "r"(abase + ks * 2048),
                                    "r"(fx), "r"(fy), "r"(fz), "r"(fw));
                }
            }
            MBAR_ARRIVE(sb + OFF_FULL + slot * 8);

#pragma unroll
            for (int i = 0; i < 16; ++i) v[i] = vn[i];
        }
    } else {
        // ===================== consumer =====================
        const int wm = wid & 1, wn = wid >> 1;       // 2 M-warps x 4 N-warps
        const int gid = lane >> 2, tig = lane & 3;

        float acc[2][4][4];
#pragma unroll
        for (int mt = 0; mt < 2; ++mt)
#pragma unroll
            for (int nt = 0; nt < 4; ++nt)
#pragma unroll
                for (int j = 0; j < 4; ++j) acc[mt][nt][j] = 0.f;
        int cnt[4] = {0, 0, 0, 0};

        const uint32_t aoff0 = (uint32_t)((wm * 2 + 0) * 512 + lane * 16);
        const uint32_t aoff1 = (uint32_t)((wm * 2 + 1) * 512 + lane * 16);
        const uint32_t boffc = (uint32_t)((wn * 32 + gid * 4) * 4);

#pragma unroll 1
        for (int s = 0; s < NN / 32; ++s) {
            const int slot = s & 3;
            MBAR_WAIT(sb + OFF_FULL + slot * 8, (s >> 2) & 1);

            uint32_t rm[4];
#pragma unroll
            for (int j = 0; j < 4; ++j) {
                rm[j] = *(const uint32_t*)(smc + OFF_MASK +
                                           (slot * 64 + wm * 32 + gid + 8 * j) * 4);
                cnt[j] += __popc(rm[j]);
            }

            const uint32_t yb = sb + OFF_Y + slot * STG_Y;
            const uint32_t ab = sb + OFF_A + slot * STG_A;
#pragma unroll
            for (int ks = 0; ks < 4; ++ks) {
                const int k0 = ks * 8;
                const int p0 = k0 + tig, p1 = p0 + 4;
                uint32_t a0[4], a1[4], b0[4], b1[4];
                asm volatile("ld.shared.v4.b32 {%0,%1,%2,%3}, [%4];"
                             : "=r"(a0[0]), "=r"(a0[1]), "=r"(a0[2]), "=r"(a0[3])
                             : "r"(ab + ks * 2048 + aoff0));
                asm volatile("ld.shared.v4.b32 {%0,%1,%2,%3}, [%4];"
                             : "=r"(a1[0]), "=r"(a1[1]), "=r"(a1[2]), "=r"(a1[3])
                             : "r"(ab + ks * 2048 + aoff1));
                asm volatile("ld.shared.v4.b32 {%0,%1,%2,%3}, [%4];"
                             : "=r"(b0[0]), "=r"(b0[1]), "=r"(b0[2]), "=r"(b0[3])
                             : "r"(yb + (uint32_t)(p0 * 136 * 4) + boffc));
                asm volatile("ld.shared.v4.b32 {%0,%1,%2,%3}, [%4];"
                             : "=r"(b1[0]), "=r"(b1[1]), "=r"(b1[2]), "=r"(b1[3])
                             : "r"(yb + (uint32_t)(p1 * 136 * 4) + boffc));
#pragma unroll
                for (int nt = 0; nt < 4; ++nt) {
                    uint32_t bf[2] = {b0[nt], b1[nt]};
                    mma_tf32(acc[0][nt], a0, bf, acc[0][nt]);
                    mma_tf32(acc[1][nt], a1, bf, acc[1][nt]);
                }
            }
            MBAR_ARRIVE(sb + OFF_EMPTY + slot * 8);
        }

        // epilogue: counts live in regs (cnt[2*mt+h] = row wm*32+mt*16+gid+8h)
#pragma unroll
        for (int mt = 0; mt < 2; ++mt)
#pragma unroll
            for (int h = 0; h < 2; ++h) {
                int r = wm * 32 + mt * 16 + gid + 8 * h;
                float c = (float)cnt[2 * mt + h];
                float inv = (c > 0.f) ? (1.f / c) : 1.f;
#pragma unroll
                for (int nt = 0; nt < 4; ++nt) {
                    int cidx = wn * 32 + nt * 8 + 2 * tig;
                    float2 bv = *(const float2*)&bias[cidx];
                    float v0 = fmaxf(acc[mt][nt][2 * h + 0] * inv + bv.x, 0.f);
                    float v1 = fmaxf(acc[mt][nt][2 * h + 1] * inv + bv.y, 0.f);
                    *(float2*)&out[((long)b * EE + eb + r) * FF + cidx] =
                        make_float2(v0, v1);
                }
            }
    }
}

// ---------------- launch ----------------
extern "C" void kernel_launch(void* const* d_in, const int* in_sizes, int n_in,
                              void* d_out, int out_size) {
    const float* X = (const float*)d_in[0];     // node_embeddings [B,N,F]
    const float* adj = (const float*)d_in[1];   // adj [B,E,N]
    const float* W = (const float*)d_in[2];     // W [F,F]
    const float* bias = (const float*)d_in[3];  // b [F]
    float* out = (float*)d_out;

    cudaFuncSetAttribute(k_xw, cudaFuncAttributeMaxDynamicSharedMemorySize, A_SMEM_BYTES);
    cudaFuncSetAttribute(k_agg, cudaFuncAttributeMaxDynamicSharedMemorySize, B_SMEM_BYTES);

    k_xw<<<(BB * NN) / 64, 256, A_SMEM_BYTES>>>(X, W);
    k_agg<<<dim3(EE / 64, BB), 384, B_SMEM_BYTES>>>(adj, bias, out);
}

// round 12
// speedup vs baseline: 1.0481x; 1.0481x over previous
#include <cuda_runtime.h>
#include <cuda_fp16.h>
#include <cstdint>

#define BB 8
#define EE 2048
#define NN 2048
#define FF 128

// Y^T scratch: [b][f][node], fp16 (4 MiB). node contiguous -> B-fragment K-pairs.
__device__ __half g_Yt[BB * FF * NN];

// ---------------- helpers ----------------
__device__ __forceinline__ uint32_t smem_u32(const void* p) {
    uint32_t a;
    asm("{ .reg .u64 t; cvta.to.shared.u64 t, %1; cvt.u32.u64 %0, t; }"
        : "=r"(a) : "l"(p));
    return a;
}
__device__ __forceinline__ uint32_t f2tf32(float x) {
    uint32_t r;
    asm("cvt.rna.tf32.f32 %0, %1;" : "=r"(r) : "f"(x));
    return r;
}
__device__ __forceinline__ void mma_tf32(float d[4], const uint32_t a[4],
                                         const uint32_t b[2], const float c[4]) {
    asm volatile(
        "mma.sync.aligned.m16n8k8.row.col.f32.tf32.tf32.f32 "
        "{%0,%1,%2,%3}, {%4,%5,%6,%7}, {%8,%9}, {%10,%11,%12,%13};"
        : "=f"(d[0]), "=f"(d[1]), "=f"(d[2]), "=f"(d[3])
        : "r"(a[0]), "r"(a[1]), "r"(a[2]), "r"(a[3]),
          "r"(b[0]), "r"(b[1]),
          "f"(c[0]), "f"(c[1]), "f"(c[2]), "f"(c[3]));
}
__device__ __forceinline__ void mma_f16(float d[4], const uint32_t a[4],
                                        const uint32_t b[2], const float c[4]) {
    asm volatile(
        "mma.sync.aligned.m16n8k16.row.col.f32.f16.f16.f32 "
        "{%0,%1,%2,%3}, {%4,%5,%6,%7}, {%8,%9}, {%10,%11,%12,%13};"
        : "=f"(d[0]), "=f"(d[1]), "=f"(d[2]), "=f"(d[3])
        : "r"(a[0]), "r"(a[1]), "r"(a[2]), "r"(a[3]),
          "r"(b[0]), "r"(b[1]),
          "f"(c[0]), "f"(c[1]), "f"(c[2]), "f"(c[3]));
}
__device__ __forceinline__ void cpa16(uint32_t s, const void* g) {
    asm volatile("cp.async.cg.shared.global [%0], [%1], 16;" :: "r"(s), "l"(g));
}
__device__ __forceinline__ void cpa_commit() { asm volatile("cp.async.commit_group;"); }
template <int W> __device__ __forceinline__ void cpa_wait() {
    asm volatile("cp.async.wait_group %0;" :: "n"(W));
}

#define MBAR_INIT(addr, cnt) \
    asm volatile("mbarrier.init.shared.b64 [%0], %1;" :: "r"((uint32_t)(addr)), "r"((uint32_t)(cnt)) : "memory")
#define MBAR_ARRIVE(addr) \
    asm volatile("mbarrier.arrive.shared.b64 _, [%0];" :: "r"((uint32_t)(addr)) : "memory")
#define MBAR_WAIT(addr, ph) do {                                                     \
    uint32_t _a = (uint32_t)(addr), _p = (uint32_t)(ph);                             \
    asm volatile("{\n\t.reg .pred P;\n\t"                                            \
        "WL%=:\n\t"                                                                  \
        "mbarrier.try_wait.parity.acquire.cta.shared::cta.b64 P, [%0], %1, 0x989680;\n\t" \
        "@P bra.uni WD%=;\n\t"                                                       \
        "bra.uni WL%=;\n\t"                                                          \
        "WD%=:\n\t}" :: "r"(_a), "r"(_p) : "memory");                                \
} while (0)
#define CP_MBAR_ARRIVE(addr) \
    asm volatile("cp.async.mbarrier.arrive.shared::cta.b64 [%0];" :: "r"((uint32_t)(addr)) : "memory")

// half2 {1.0 or 0.0, 1.0 or 0.0} from 2 mask bits (bit0 -> lo, bit1 -> hi)
__device__ __forceinline__ uint32_t pair_h2(uint32_t v2) {
    return ((v2 & 1u) * 0x3C00u) | ((v2 >> 1) * 0x3C000000u);
}

// ---------------- Kernel A: Yt = fp16(W @ X^T) per batch ----------------
// CTA: 128 f-rows x 64 node-cols, K=128. A-frag from W rows, B-frag from X rows.
#define A_SMEM_BYTES ((64 + 128) * 132 * 4)

__global__ __launch_bounds__(256, 2) void k_xw(const float* __restrict__ X,
                                               const float* __restrict__ W) {
    extern __shared__ float sm[];
    float* sX = sm;              // [64][132]   node rows
    float* sW = sm + 64 * 132;   // [128][132]  f rows
    const int tid = threadIdx.x;
    const long rbase = (long)blockIdx.x * 64;      // b*2048 + nbase
    const int b = (int)(rbase >> 11);
    const int nbase = (int)(rbase & 2047);

    uint32_t sXb = (uint32_t)__cvta_generic_to_shared(sX);
    uint32_t sWb = (uint32_t)__cvta_generic_to_shared(sW);

#pragma unroll
    for (int i = 0; i < 8; ++i) {
        int id = tid + i * 256;
        int r = id >> 5;
        int c4 = (id & 31) * 4;
        cpa16(sXb + (uint32_t)(r * 132 + c4) * 4, X + (rbase + r) * FF + c4);
    }
#pragma unroll
    for (int i = 0; i < 16; ++i) {
        int id = tid + i * 256;
        int r = id >> 5;
        int c4 = (id & 31) * 4;
        cpa16(sWb + (uint32_t)(r * 132 + c4) * 4, W + r * FF + c4);
    }
    cpa_commit();
    cpa_wait<0>();
    __syncthreads();

    const int lane = tid & 31, warp = tid >> 5;
    const int wm = warp >> 1, wn = warp & 1;
    const int gid = lane >> 2, tig = lane & 3;

    float acc[2][4][4];
#pragma unroll
    for (int mt = 0; mt < 2; ++mt)
#pragma unroll
        for (int nt = 0; nt < 4; ++nt)
#pragma unroll
            for (int j = 0; j < 4; ++j) acc[mt][nt][j] = 0.f;

#pragma unroll
    for (int ks = 0; ks < 16; ++ks) {
        const int k0 = ks * 8;
        uint32_t af[2][4];
#pragma unroll
        for (int mt = 0; mt < 2; ++mt) {          // A rows = f, from sW
            int f = wm * 32 + mt * 16 + gid;
            af[mt][0] = f2tf32(sW[f * 132 + k0 + tig]);
            af[mt][1] = f2tf32(sW[(f + 8) * 132 + k0 + tig]);
            af[mt][2] = f2tf32(sW[f * 132 + k0 + tig + 4]);
            af[mt][3] = f2tf32(sW[(f + 8) * 132 + k0 + tig + 4]);
        }
        uint32_t bf[4][2];
#pragma unroll
        for (int nt = 0; nt < 4; ++nt) {          // B rows = nodes, from sX
            int n = wn * 32 + nt * 8 + gid;
            bf[nt][0] = f2tf32(sX[n * 132 + k0 + tig]);
            bf[nt][1] = f2tf32(sX[n * 132 + k0 + tig + 4]);
        }
#pragma unroll
        for (int mt = 0; mt < 2; ++mt)
#pragma unroll
            for (int nt = 0; nt < 4; ++nt)
                mma_tf32(acc[mt][nt], af[mt], bf[nt], acc[mt][nt]);
    }

    // store Yt[b][f][node] as fp16 (half2 per thread: adjacent nodes)
    __half* Ybase = g_Yt + (long)b * FF * NN;
#pragma unroll
    for (int mt = 0; mt < 2; ++mt)
#pragma unroll
        for (int h = 0; h < 2; ++h) {
            int f = wm * 32 + mt * 16 + gid + 8 * h;
#pragma unroll
            for (int nt = 0; nt < 4; ++nt) {
                int n0 = wn * 32 + nt * 8 + 2 * tig;
                __half2 hv = __floats2half2_rn(acc[mt][nt][2 * h + 0],
                                               acc[mt][nt][2 * h + 1]);
                *(__half2*)&Ybase[(long)f * NN + nbase + n0] = hv;
            }
        }
}

// ---------------- Kernel B: fp16 warp-specialized pipelined masked GEMM ----------------
// 384 threads: warps 0-7 consumers (64 edges x 128 feats), warps 8-11 producers.
// KC=64 nodes/chunk, 32 chunks, 4-stage ring.
#define KC 64
#define Y_ROW 144
#define STG_Y (128 * Y_ROW)                  // 18432
#define STG_A 8192
#define OFF_Y 0
#define OFF_A (4 * STG_Y)                    // 73728
#define OFF_MASK (OFF_A + 4 * STG_A)         // 106496 (4 stages x 64 x 2 x 4B)
#define OFF_FULL (OFF_MASK + 4 * 64 * 8)     // 108544
#define OFF_EMPTY (OFF_FULL + 32)            // 108576
#define B_SMEM_BYTES (OFF_EMPTY + 32)        // 108608

__global__ __launch_bounds__(384, 2) void k_agg(const float* __restrict__ adj,
                                                const float* __restrict__ bias,
                                                float* __restrict__ out) {
    extern __shared__ char smc[];
    const uint32_t sb = smem_u32(smc);
    const int tid = threadIdx.x, wid = tid >> 5, lane = tid & 31;
    const int eb = blockIdx.x * 64, b = blockIdx.y;
    const float* adjBase = adj + ((long)b * EE + eb) * NN;
    const __half* Ytb = g_Yt + (long)b * FF * NN;

    if (tid == 0) {
#pragma unroll
        for (int i = 0; i < 4; ++i) {
            // cp.async.mbarrier.arrive (non-.noinc) is SELF-BALANCING: it raises
            // pending at issue and lowers it at completion — net zero vs init.
            // Only the single explicit arrive (producer thread 0) counts here;
            // the phase flip additionally waits for all tracked cp.asyncs.
            MBAR_INIT(sb + OFF_FULL + i * 8, 1);
            MBAR_INIT(sb + OFF_EMPTY + i * 8, 8);    // 8 consumer warps (lane0)
        }
    }
    __syncthreads();

    if (wid >= 8) {
        // ===================== producer =====================
        const int p = tid - 256;            // 0..127
        const int pw = p >> 5, pl = p & 31;
        // expansion role
        const int ewm = p >> 6, emt = (p >> 5) & 1, elane = p & 31;
        const int etig = elane & 3;
        const int er0 = ewm * 32 + emt * 16 + (elane >> 2);

#pragma unroll 1
        for (int s = 0; s < NN / KC; ++s) {
            const int slot = s & 3;
            MBAR_WAIT(sb + OFF_EMPTY + slot * 8, ((s >> 2) & 1) ^ 1);

            // adj chunk loads first (start DRAM latency early)
            const float* arow = adjBase + (long)(pw * 16) * NN + s * KC + pl;
            float v0[16], v1[16];
#pragma unroll
            for (int i = 0; i < 16; ++i) {
                v0[i] = arow[(long)i * NN];
                v1[i] = arow[(long)i * NN + 32];
            }

            // Y tile via cp.async: 128 f-rows x 128B, thread p owns row f=p
            {
                const char* ysrc = (const char*)(Ytb + (long)p * NN + s * KC);
                uint32_t ydst = sb + OFF_Y + slot * STG_Y + (uint32_t)p * Y_ROW;
#pragma unroll
                for (int j = 0; j < 8; ++j)
                    cpa16(ydst + j * 16, ysrc + j * 16);
            }
            CP_MBAR_ARRIVE(sb + OFF_FULL + slot * 8);

            // ballots -> mask words [row][half]
#pragma unroll
            for (int i = 0; i < 16; ++i) {
                uint32_t m0 = __ballot_sync(0xffffffffu, v0[i] == -1.f);
                uint32_t m1 = __ballot_sync(0xffffffffu, v1[i] == -1.f);
                if (pl == i) {
                    uint32_t ma = sb + OFF_MASK + (uint32_t)(slot * 64 + pw * 16 + i) * 8;
                    asm volatile("st.shared.v2.b32 [%0], {%1,%2};"
                                 :: "r"(ma), "r"(m0), "r"(m1));
                }
            }
            asm volatile("bar.sync 1, 128;" ::: "memory");

            // expand masks -> fp16 A fragments
            {
                uint32_t mb = sb + OFF_MASK + (uint32_t)(slot * 64) * 8;
                uint32_t r0h0, r0h1, r1h0, r1h1;
                asm volatile("ld.shared.v2.b32 {%0,%1}, [%2];"
                             : "=r"(r0h0), "=r"(r0h1) : "r"(mb + (uint32_t)er0 * 8));
                asm volatile("ld.shared.v2.b32 {%0,%1}, [%2];"
                             : "=r"(r1h0), "=r"(r1h1) : "r"(mb + (uint32_t)(er0 + 8) * 8));
                uint32_t abase = sb + OFF_A + slot * STG_A +
                                 (uint32_t)((ewm * 2 + emt) * 32 + elane) * 16;
#pragma unroll
                for (int t = 0; t < 4; ++t) {
                    uint32_t w0 = (t < 2) ? r0h0 : r0h1;
                    uint32_t w1 = (t < 2) ? r1h0 : r1h1;
                    int sh = (t & 1) * 16 + 2 * etig;
                    uint32_t a0 = pair_h2((w0 >> sh) & 3u);
                    uint32_t a1 = pair_h2((w1 >> sh) & 3u);
                    uint32_t a2 = pair_h2((w0 >> (sh + 8)) & 3u);
                    uint32_t a3 = pair_h2((w1 >> (sh + 8)) & 3u);
                    asm volatile("st.shared.v4.b32 [%0], {%1,%2,%3,%4};"
                                 :: "r"(abase + (uint32_t)t * 2048),
                                    "r"(a0), "r"(a1), "r"(a2), "r"(a3));
                }
            }
            asm volatile("bar.sync 1, 128;" ::: "memory");
            if (p == 0) MBAR_ARRIVE(sb + OFF_FULL + slot * 8);
        }
    } else {
        // ===================== consumer =====================
        const int wm = wid & 1, wn = wid >> 1;       // 2 M-warps x 4 N-warps
        const int gid = lane >> 2, tig = lane & 3;

        float acc[2][4][4];
#pragma unroll
        for (int mt = 0; mt < 2; ++mt)
#pragma unroll
            for (int nt = 0; nt < 4; ++nt)
#pragma unroll
                for (int j = 0; j < 4; ++j) acc[mt][nt][j] = 0.f;
        int cnt[4] = {0, 0, 0, 0};

        const uint32_t aoffm0 = (uint32_t)((wm * 2 + 0) * 32 + lane) * 16;
        const uint32_t aoffm1 = (uint32_t)((wm * 2 + 1) * 32 + lane) * 16;

#pragma unroll 1
        for (int s = 0; s < NN / KC; ++s) {
            const int slot = s & 3;
            MBAR_WAIT(sb + OFF_FULL + slot * 8, (s >> 2) & 1);

            // per-row counts from mask words
#pragma unroll
            for (int j = 0; j < 4; ++j) {
                int row = wm * 32 + gid + 8 * j;
                uint32_t w0, w1;
                asm volatile("ld.shared.v2.b32 {%0,%1}, [%2];"
                             : "=r"(w0), "=r"(w1)
                             : "r"(sb + OFF_MASK + (uint32_t)(slot * 64 + row) * 8));
                cnt[j] += __popc(w0) + __popc(w1);
            }

            const uint32_t yb = sb + OFF_Y + slot * STG_Y;
            const uint32_t ab = sb + OFF_A + slot * STG_A;
#pragma unroll
            for (int t = 0; t < 4; ++t) {
                uint32_t a0[4], a1[4];
                asm volatile("ld.shared.v4.b32 {%0,%1,%2,%3}, [%4];"
                             : "=r"(a0[0]), "=r"(a0[1]), "=r"(a0[2]), "=r"(a0[3])
                             : "r"(ab + (uint32_t)t * 2048 + aoffm0));
                asm volatile("ld.shared.v4.b32 {%0,%1,%2,%3}, [%4];"
                             : "=r"(a1[0]), "=r"(a1[1]), "=r"(a1[2]), "=r"(a1[3])
                             : "r"(ab + (uint32_t)t * 2048 + aoffm1));
#pragma unroll
                for (int nt = 0; nt < 4; ++nt) {
                    int f = wn * 32 + nt * 8 + gid;
                    uint32_t baddr = yb + (uint32_t)f * Y_ROW + (uint32_t)(t * 8 + tig) * 4;
                    uint32_t bf[2];
                    asm volatile("ld.shared.b32 %0, [%1];" : "=r"(bf[0]) : "r"(baddr));
                    asm volatile("ld.shared.b32 %0, [%1];" : "=r"(bf[1]) : "r"(baddr + 16));
                    mma_f16(acc[0][nt], a0, bf, acc[0][nt]);
                    mma_f16(acc[1][nt], a1, bf, acc[1][nt]);
                }
            }
            __syncwarp();
            if (lane == 0) MBAR_ARRIVE(sb + OFF_EMPTY + slot * 8);
        }

        // epilogue
#pragma unroll
        for (int mt = 0; mt < 2; ++mt)
#pragma unroll
            for (int h = 0; h < 2; ++h) {
                int r = wm * 32 + mt * 16 + gid + 8 * h;
                float c = (float)cnt[2 * mt + h];
                float inv = (c > 0.f) ? (1.f / c) : 1.f;
#pragma unroll
                for (int nt = 0; nt < 4; ++nt) {
                    int cidx = wn * 32 + nt * 8 + 2 * tig;
                    float2 bv = *(const float2*)&bias[cidx];
                    float v0 = fmaxf(acc[mt][nt][2 * h + 0] * inv + bv.x, 0.f);
                    float v1 = fmaxf(acc[mt][nt][2 * h + 1] * inv + bv.y, 0.f);
                    *(float2*)&out[((long)b * EE + eb + r) * FF + cidx] =
                        make_float2(v0, v1);
                }
            }
    }
}

// ---------------- launch ----------------
extern "C" void kernel_launch(void* const* d_in, const int* in_sizes, int n_in,
                              void* d_out, int out_size) {
    const float* X = (const float*)d_in[0];     // node_embeddings [B,N,F]
    const float* adj = (const float*)d_in[1];   // adj [B,E,N]
    const float* W = (const float*)d_in[2];     // W [F,F]
    const float* bias = (const float*)d_in[3];  // b [F]
    float* out = (float*)d_out;

    cudaFuncSetAttribute(k_xw, cudaFuncAttributeMaxDynamicSharedMemorySize, A_SMEM_BYTES);
    cudaFuncSetAttribute(k_agg, cudaFuncAttributeMaxDynamicSharedMemorySize, B_SMEM_BYTES);

    k_xw<<<(BB * NN) / 64, 256, A_SMEM_BYTES>>>(X, W);
    k_agg<<<dim3(EE / 64, BB), 384, B_SMEM_BYTES>>>(adj, bias, out);
}

// round 13
// speedup vs baseline: 1.1563x; 1.1032x over previous
#include <cuda_runtime.h>
#include <cuda_fp16.h>
#include <cstdint>

#define BB 8
#define EE 2048
#define NN 2048
#define FF 128

// Y^T scratch: [b][f][node], fp16 (4 MiB). node contiguous -> B-fragment K-pairs.
__device__ __half g_Yt[BB * FF * NN];

// ---------------- helpers ----------------
__device__ __forceinline__ uint32_t smem_u32(const void* p) {
    uint32_t a;
    asm("{ .reg .u64 t; cvta.to.shared.u64 t, %1; cvt.u32.u64 %0, t; }"
        : "=r"(a) : "l"(p));
    return a;
}
__device__ __forceinline__ uint32_t f2tf32(float x) {
    uint32_t r;
    asm("cvt.rna.tf32.f32 %0, %1;" : "=r"(r) : "f"(x));
    return r;
}
__device__ __forceinline__ void mma_tf32(float d[4], const uint32_t a[4],
                                         const uint32_t b[2], const float c[4]) {
    asm volatile(
        "mma.sync.aligned.m16n8k8.row.col.f32.tf32.tf32.f32 "
        "{%0,%1,%2,%3}, {%4,%5,%6,%7}, {%8,%9}, {%10,%11,%12,%13};"
        : "=f"(d[0]), "=f"(d[1]), "=f"(d[2]), "=f"(d[3])
        : "r"(a[0]), "r"(a[1]), "r"(a[2]), "r"(a[3]),
          "r"(b[0]), "r"(b[1]),
          "f"(c[0]), "f"(c[1]), "f"(c[2]), "f"(c[3]));
}
__device__ __forceinline__ void mma_f16(float d[4], const uint32_t a[4],
                                        const uint32_t b0, const uint32_t b1,
                                        const float c[4]) {
    asm volatile(
        "mma.sync.aligned.m16n8k16.row.col.f32.f16.f16.f32 "
        "{%0,%1,%2,%3}, {%4,%5,%6,%7}, {%8,%9}, {%10,%11,%12,%13};"
        : "=f"(d[0]), "=f"(d[1]), "=f"(d[2]), "=f"(d[3])
        : "r"(a[0]), "r"(a[1]), "r"(a[2]), "r"(a[3]),
          "r"(b0), "r"(b1),
          "f"(c[0]), "f"(c[1]), "f"(c[2]), "f"(c[3]));
}
__device__ __forceinline__ void ldsm_x4(uint32_t& d0, uint32_t& d1,
                                        uint32_t& d2, uint32_t& d3, uint32_t addr) {
    asm volatile("ldmatrix.sync.aligned.m8n8.x4.shared.b16 {%0,%1,%2,%3}, [%4];"
                 : "=r"(d0), "=r"(d1), "=r"(d2), "=r"(d3) : "r"(addr));
}
__device__ __forceinline__ void cpa16(uint32_t s, const void* g) {
    asm volatile("cp.async.cg.shared.global [%0], [%1], 16;" :: "r"(s), "l"(g));
}
__device__ __forceinline__ void cpa_commit() { asm volatile("cp.async.commit_group;"); }
template <int W> __device__ __forceinline__ void cpa_wait() {
    asm volatile("cp.async.wait_group %0;" :: "n"(W));
}

#define MBAR_INIT(addr, cnt) \
    asm volatile("mbarrier.init.shared.b64 [%0], %1;" :: "r"((uint32_t)(addr)), "r"((uint32_t)(cnt)) : "memory")
#define MBAR_ARRIVE(addr) \
    asm volatile("mbarrier.arrive.shared.b64 _, [%0];" :: "r"((uint32_t)(addr)) : "memory")
#define MBAR_WAIT(addr, ph) do {                                                     \
    uint32_t _a = (uint32_t)(addr), _p = (uint32_t)(ph);                             \
    asm volatile("{\n\t.reg .pred P;\n\t"                                            \
        "WL%=:\n\t"                                                                  \
        "mbarrier.try_wait.parity.acquire.cta.shared::cta.b64 P, [%0], %1, 0x989680;\n\t" \
        "@P bra.uni WD%=;\n\t"                                                       \
        "bra.uni WL%=;\n\t"                                                          \
        "WD%=:\n\t}" :: "r"(_a), "r"(_p) : "memory");                                \
} while (0)
#define CP_MBAR_ARRIVE(addr) \
    asm volatile("cp.async.mbarrier.arrive.shared::cta.b64 [%0];" :: "r"((uint32_t)(addr)) : "memory")

// half2 {1.0 or 0.0, 1.0 or 0.0} from 2 mask bits (bit0 -> lo, bit1 -> hi)
__device__ __forceinline__ uint32_t pair_h2(uint32_t v2) {
    return ((v2 & 1u) * 0x3C00u) | ((v2 >> 1) * 0x3C000000u);
}

// ---------------- Kernel A: Yt = fp16(W @ X^T) per batch ----------------
#define A_SMEM_BYTES ((64 + 128) * 132 * 4)

__global__ __launch_bounds__(256, 2) void k_xw(const float* __restrict__ X,
                                               const float* __restrict__ W) {
    extern __shared__ float sm[];
    float* sX = sm;              // [64][132]   node rows
    float* sW = sm + 64 * 132;   // [128][132]  f rows
    const int tid = threadIdx.x;
    const long rbase = (long)blockIdx.x * 64;      // b*2048 + nbase
    const int b = (int)(rbase >> 11);
    const int nbase = (int)(rbase & 2047);

    uint32_t sXb = (uint32_t)__cvta_generic_to_shared(sX);
    uint32_t sWb = (uint32_t)__cvta_generic_to_shared(sW);

#pragma unroll
    for (int i = 0; i < 8; ++i) {
        int id = tid + i * 256;
        int r = id >> 5;
        int c4 = (id & 31) * 4;
        cpa16(sXb + (uint32_t)(r * 132 + c4) * 4, X + (rbase + r) * FF + c4);
    }
#pragma unroll
    for (int i = 0; i < 16; ++i) {
        int id = tid + i * 256;
        int r = id >> 5;
        int c4 = (id & 31) * 4;
        cpa16(sWb + (uint32_t)(r * 132 + c4) * 4, W + r * FF + c4);
    }
    cpa_commit();
    cpa_wait<0>();
    __syncthreads();

    const int lane = tid & 31, warp = tid >> 5;
    const int wm = warp >> 1, wn = warp & 1;
    const int gid = lane >> 2, tig = lane & 3;

    float acc[2][4][4];
#pragma unroll
    for (int mt = 0; mt < 2; ++mt)
#pragma unroll
        for (int nt = 0; nt < 4; ++nt)
#pragma unroll
            for (int j = 0; j < 4; ++j) acc[mt][nt][j] = 0.f;

#pragma unroll
    for (int ks = 0; ks < 16; ++ks) {
        const int k0 = ks * 8;
        uint32_t af[2][4];
#pragma unroll
        for (int mt = 0; mt < 2; ++mt) {          // A rows = f, from sW
            int f = wm * 32 + mt * 16 + gid;
            af[mt][0] = f2tf32(sW[f * 132 + k0 + tig]);
            af[mt][1] = f2tf32(sW[(f + 8) * 132 + k0 + tig]);
            af[mt][2] = f2tf32(sW[f * 132 + k0 + tig + 4]);
            af[mt][3] = f2tf32(sW[(f + 8) * 132 + k0 + tig + 4]);
        }
        uint32_t bf[4][2];
#pragma unroll
        for (int nt = 0; nt < 4; ++nt) {          // B rows = nodes, from sX
            int n = wn * 32 + nt * 8 + gid;
            bf[nt][0] = f2tf32(sX[n * 132 + k0 + tig]);
            bf[nt][1] = f2tf32(sX[n * 132 + k0 + tig + 4]);
        }
#pragma unroll
        for (int mt = 0; mt < 2; ++mt)
#pragma unroll
            for (int nt = 0; nt < 4; ++nt)
                mma_tf32(acc[mt][nt], af[mt], bf[nt], acc[mt][nt]);
    }

    // store Yt[b][f][node] as fp16 (half2 per thread: adjacent nodes)
    __half* Ybase = g_Yt + (long)b * FF * NN;
#pragma unroll
    for (int mt = 0; mt < 2; ++mt)
#pragma unroll
        for (int h = 0; h < 2; ++h) {
            int f = wm * 32 + mt * 16 + gid + 8 * h;
#pragma unroll
            for (int nt = 0; nt < 4; ++nt) {
                int n0 = wn * 32 + nt * 8 + 2 * tig;
                __half2 hv = __floats2half2_rn(acc[mt][nt][2 * h + 0],
                                               acc[mt][nt][2 * h + 1]);
                *(__half2*)&Ybase[(long)f * NN + nbase + n0] = hv;
            }
        }
}

// ---------------- Kernel B: fp16 warp-specialized pipelined masked GEMM ----------------
// 256 threads: warps 0-3 consumers (each: M=64 full x N=32), warps 4-7 producers.
// KC=64 nodes/chunk, 32 chunks, 4-stage ring.
// Stage: Y fp16 [128 f][64 nodes] rows padded 144B; A frags [t4][mt4][lane32]x16B;
//        masks [64 rows][2 halves] u32.
#define KC 64
#define Y_ROW 144
#define STG_Y (128 * Y_ROW)                  // 18432
#define STG_A 8192
#define OFF_Y 0
#define OFF_A (4 * STG_Y)                    // 73728
#define OFF_MASK (OFF_A + 4 * STG_A)         // 106496
#define OFF_FULL (OFF_MASK + 4 * 64 * 8)     // 108544
#define OFF_EMPTY (OFF_FULL + 32)            // 108576
#define B_SMEM_BYTES (OFF_EMPTY + 32)        // 108608

__global__ __launch_bounds__(256, 2) void k_agg(const float* __restrict__ adj,
                                                const float* __restrict__ bias,
                                                float* __restrict__ out) {
    extern __shared__ char smc[];
    const uint32_t sb = smem_u32(smc);
    const int tid = threadIdx.x, wid = tid >> 5, lane = tid & 31;
    const int eb = blockIdx.x * 64, b = blockIdx.y;
    const float* adjBase = adj + ((long)b * EE + eb) * NN;
    const __half* Ytb = g_Yt + (long)b * FF * NN;

    if (tid == 0) {
#pragma unroll
        for (int i = 0; i < 4; ++i) {
            // cp.async.mbarrier.arrive is self-balancing; explicit arrives: 4 producer warps.
            MBAR_INIT(sb + OFF_FULL + i * 8, 4);
            MBAR_INIT(sb + OFF_EMPTY + i * 8, 4);    // 4 consumer warps (lane0)
        }
    }
    __syncthreads();

    if (wid >= 4) {
        // ===================== producer =====================
        const int p = tid - 128;            // 0..127
        const int pw = p >> 5, pl = p & 31;
        // expansion role: mt = p>>5, lane = p&31
        const int emt = p >> 5, elane = p & 31;
        const int etig = elane & 3;
        const int er0 = emt * 16 + (elane >> 2);

        const float* arow = adjBase + (long)(pw * 16) * NN + pl;
        float v0[16], v1[16], vn0[16], vn1[16];
#pragma unroll
        for (int i = 0; i < 16; ++i) {      // chunk 0
            v0[i] = arow[(long)i * NN];
            v1[i] = arow[(long)i * NN + 32];
        }

#pragma unroll 1
        for (int s = 0; s < NN / KC; ++s) {
            const int slot = s & 3;
            MBAR_WAIT(sb + OFF_EMPTY + slot * 8, ((s >> 2) & 1) ^ 1);

            // Y tile via cp.async: thread p owns f-row p (128 B)
            {
                const char* ysrc = (const char*)(Ytb + (long)p * NN + s * KC);
                uint32_t ydst = sb + OFF_Y + slot * STG_Y + (uint32_t)p * Y_ROW;
#pragma unroll
                for (int j = 0; j < 8; ++j)
                    cpa16(ydst + j * 16, ysrc + j * 16);
            }
            CP_MBAR_ARRIVE(sb + OFF_FULL + slot * 8);

            // prefetch next adj chunk (hide DRAM latency off the pacing path)
            if (s + 1 < NN / KC) {
                const float* an = arow + (s + 1) * KC;
#pragma unroll
                for (int i = 0; i < 16; ++i) {
                    vn0[i] = an[(long)i * NN];
                    vn1[i] = an[(long)i * NN + 32];
                }
            }

            // ballots -> mask words [row][half]
#pragma unroll
            for (int i = 0; i < 16; ++i) {
                uint32_t m0 = __ballot_sync(0xffffffffu, v0[i] == -1.f);
                uint32_t m1 = __ballot_sync(0xffffffffu, v1[i] == -1.f);
                if (pl == i) {
                    uint32_t ma = sb + OFF_MASK + (uint32_t)(slot * 64 + pw * 16 + i) * 8;
                    asm volatile("st.shared.v2.b32 [%0], {%1,%2};"
                                 :: "r"(ma), "r"(m0), "r"(m1));
                }
            }
            asm volatile("bar.sync 1, 128;" ::: "memory");   // masks visible cross-warp

            // expand masks -> fp16 A fragments [t][mt][lane]
            {
                uint32_t mb = sb + OFF_MASK + (uint32_t)(slot * 64) * 8;
                uint32_t r0h0, r0h1, r1h0, r1h1;
                asm volatile("ld.shared.v2.b32 {%0,%1}, [%2];"
                             : "=r"(r0h0), "=r"(r0h1) : "r"(mb + (uint32_t)er0 * 8));
                asm volatile("ld.shared.v2.b32 {%0,%1}, [%2];"
                             : "=r"(r1h0), "=r"(r1h1) : "r"(mb + (uint32_t)(er0 + 8) * 8));
                uint32_t abase = sb + OFF_A + slot * STG_A +
                                 (uint32_t)(emt * 32 + elane) * 16;
#pragma unroll
                for (int t = 0; t < 4; ++t) {
                    uint32_t w0 = (t < 2) ? r0h0 : r0h1;
                    uint32_t w1 = (t < 2) ? r1h0 : r1h1;
                    int sh = (t & 1) * 16 + 2 * etig;
                    uint32_t a0 = pair_h2((w0 >> sh) & 3u);
                    uint32_t a1 = pair_h2((w1 >> sh) & 3u);
                    uint32_t a2 = pair_h2((w0 >> (sh + 8)) & 3u);
                    uint32_t a3 = pair_h2((w1 >> (sh + 8)) & 3u);
                    asm volatile("st.shared.v4.b32 [%0], {%1,%2,%3,%4};"
                                 :: "r"(abase + (uint32_t)t * 2048),
                                    "r"(a0), "r"(a1), "r"(a2), "r"(a3));
                }
            }
            __syncwarp();
            if (pl == 0) MBAR_ARRIVE(sb + OFF_FULL + slot * 8);

#pragma unroll
            for (int i = 0; i < 16; ++i) {
                v0[i] = vn0[i];
                v1[i] = vn1[i];
            }
        }
    } else {
        // ===================== consumer =====================
        const int wn = wid;                       // f block: wn*32 .. wn*32+31
        const int gid = lane >> 2, tig = lane & 3;

        float acc[4][4][4];
#pragma unroll
        for (int mt = 0; mt < 4; ++mt)
#pragma unroll
            for (int nt = 0; nt < 4; ++nt)
#pragma unroll
                for (int j = 0; j < 4; ++j) acc[mt][nt][j] = 0.f;
        int cnt[8] = {0, 0, 0, 0, 0, 0, 0, 0};

        // ldmatrix per-lane offsets: matrix m=lane>>3: fr = wn*32+(m>>1)*8+(lane&7),
        // k-byte = (m&1)*16. Second x4 covers fr+16.
        const uint32_t lm1 = (uint32_t)((wn * 32 + ((lane >> 4) & 1) * 8 + (lane & 7)) * Y_ROW +
                                        ((lane >> 3) & 1) * 16);
        const uint32_t lm2 = lm1 + 16 * Y_ROW;
        const uint32_t aoff = (uint32_t)lane * 16;

#pragma unroll 1
        for (int s = 0; s < NN / KC; ++s) {
            const int slot = s & 3;
            MBAR_WAIT(sb + OFF_FULL + slot * 8, (s >> 2) & 1);

            // per-row counts (rows gid+8j)
#pragma unroll
            for (int j = 0; j < 8; ++j) {
                uint32_t w0, w1;
                asm volatile("ld.shared.v2.b32 {%0,%1}, [%2];"
                             : "=r"(w0), "=r"(w1)
                             : "r"(sb + OFF_MASK + (uint32_t)(slot * 64 + gid + 8 * j) * 8));
                cnt[j] += __popc(w0) + __popc(w1);
            }

            const uint32_t yb = sb + OFF_Y + slot * STG_Y;
            const uint32_t ab = sb + OFF_A + slot * STG_A;
#pragma unroll
            for (int t = 0; t < 4; ++t) {
                uint32_t a[4][4];
#pragma unroll
                for (int mt = 0; mt < 4; ++mt)
                    asm volatile("ld.shared.v4.b32 {%0,%1,%2,%3}, [%4];"
                                 : "=r"(a[mt][0]), "=r"(a[mt][1]),
                                   "=r"(a[mt][2]), "=r"(a[mt][3])
                                 : "r"(ab + (uint32_t)t * 2048 + (uint32_t)mt * 512 + aoff));
                uint32_t b01[4], b23[4];
                ldsm_x4(b01[0], b01[1], b01[2], b01[3], yb + (uint32_t)t * 32 + lm1);
                ldsm_x4(b23[0], b23[1], b23[2], b23[3], yb + (uint32_t)t * 32 + lm2);
#pragma unroll
                for (int mt = 0; mt < 4; ++mt) {
                    mma_f16(acc[mt][0], a[mt], b01[0], b01[1], acc[mt][0]);
                    mma_f16(acc[mt][1], a[mt], b01[2], b01[3], acc[mt][1]);
                    mma_f16(acc[mt][2], a[mt], b23[0], b23[1], acc[mt][2]);
                    mma_f16(acc[mt][3], a[mt], b23[2], b23[3], acc[mt][3]);
                }
            }
            __syncwarp();
            if (lane == 0) MBAR_ARRIVE(sb + OFF_EMPTY + slot * 8);
        }

        // epilogue: row r = mt*16 + gid + 8h  -> cnt[2*mt+h]
#pragma unroll
        for (int mt = 0; mt < 4; ++mt)
#pragma unroll
            for (int h = 0; h < 2; ++h) {
                int r = mt * 16 + gid + 8 * h;
                float c = (float)cnt[2 * mt + h];
                float inv = (c > 0.f) ? (1.f / c) : 1.f;
#pragma unroll
                for (int nt = 0; nt < 4; ++nt) {
                    int cidx = wn * 32 + nt * 8 + 2 * tig;
                    float2 bv = *(const float2*)&bias[cidx];
                    float v0 = fmaxf(acc[mt][nt][2 * h + 0] * inv + bv.x, 0.f);
                    float v1 = fmaxf(acc[mt][nt][2 * h + 1] * inv + bv.y, 0.f);
                    *(float2*)&out[((long)b * EE + eb + r) * FF + cidx] =
                        make_float2(v0, v1);
                }
            }
    }
}

// ---------------- launch ----------------
extern "C" void kernel_launch(void* const* d_in, const int* in_sizes, int n_in,
                              void* d_out, int out_size) {
    const float* X = (const float*)d_in[0];     // node_embeddings [B,N,F]
    const float* adj = (const float*)d_in[1];   // adj [B,E,N]
    const float* W = (const float*)d_in[2];     // W [F,F]
    const float* bias = (const float*)d_in[3];  // b [F]
    float* out = (float*)d_out;

    cudaFuncSetAttribute(k_xw, cudaFuncAttributeMaxDynamicSharedMemorySize, A_SMEM_BYTES);
    cudaFuncSetAttribute(k_agg, cudaFuncAttributeMaxDynamicSharedMemorySize, B_SMEM_BYTES);

    k_xw<<<(BB * NN) / 64, 256, A_SMEM_BYTES>>>(X, W);
    k_agg<<<dim3(EE / 64, BB), 256, B_SMEM_BYTES>>>(adj, bias, out);
}

// round 14
// speedup vs baseline: 1.1984x; 1.0364x over previous
#include <cuda_runtime.h>
#include <cuda_fp16.h>
#include <cstdint>

#define BB 8
#define EE 2048
#define NN 2048
#define FF 128

// Y^T scratch: [b][f][node], fp16 (4 MiB). node contiguous -> B-fragment K-pairs.
__device__ __half g_Yt[BB * FF * NN];

// ---------------- helpers ----------------
__device__ __forceinline__ uint32_t smem_u32(const void* p) {
    uint32_t a;
    asm("{ .reg .u64 t; cvta.to.shared.u64 t, %1; cvt.u32.u64 %0, t; }"
        : "=r"(a) : "l"(p));
    return a;
}
__device__ __forceinline__ uint32_t f2tf32(float x) {
    uint32_t r;
    asm("cvt.rna.tf32.f32 %0, %1;" : "=r"(r) : "f"(x));
    return r;
}
__device__ __forceinline__ void mma_tf32(float d[4], const uint32_t a[4],
                                         const uint32_t b[2], const float c[4]) {
    asm volatile(
        "mma.sync.aligned.m16n8k8.row.col.f32.tf32.tf32.f32 "
        "{%0,%1,%2,%3}, {%4,%5,%6,%7}, {%8,%9}, {%10,%11,%12,%13};"
        : "=f"(d[0]), "=f"(d[1]), "=f"(d[2]), "=f"(d[3])
        : "r"(a[0]), "r"(a[1]), "r"(a[2]), "r"(a[3]),
          "r"(b[0]), "r"(b[1]),
          "f"(c[0]), "f"(c[1]), "f"(c[2]), "f"(c[3]));
}
__device__ __forceinline__ void mma_f16(float d[4], const uint32_t a[4],
                                        const uint32_t b0, const uint32_t b1,
                                        const float c[4]) {
    asm volatile(
        "mma.sync.aligned.m16n8k16.row.col.f32.f16.f16.f32 "
        "{%0,%1,%2,%3}, {%4,%5,%6,%7}, {%8,%9}, {%10,%11,%12,%13};"
        : "=f"(d[0]), "=f"(d[1]), "=f"(d[2]), "=f"(d[3])
        : "r"(a[0]), "r"(a[1]), "r"(a[2]), "r"(a[3]),
          "r"(b0), "r"(b1),
          "f"(c[0]), "f"(c[1]), "f"(c[2]), "f"(c[3]));
}
__device__ __forceinline__ void ldsm_x4(uint32_t& d0, uint32_t& d1,
                                        uint32_t& d2, uint32_t& d3, uint32_t addr) {
    asm volatile("ldmatrix.sync.aligned.m8n8.x4.shared.b16 {%0,%1,%2,%3}, [%4];"
                 : "=r"(d0), "=r"(d1), "=r"(d2), "=r"(d3) : "r"(addr));
}
__device__ __forceinline__ void cpa16(uint32_t s, const void* g) {
    asm volatile("cp.async.cg.shared.global [%0], [%1], 16;" :: "r"(s), "l"(g));
}
__device__ __forceinline__ void cpa_commit() { asm volatile("cp.async.commit_group;"); }
template <int W> __device__ __forceinline__ void cpa_wait() {
    asm volatile("cp.async.wait_group %0;" :: "n"(W));
}

#define MBAR_INIT(addr, cnt) \
    asm volatile("mbarrier.init.shared.b64 [%0], %1;" :: "r"((uint32_t)(addr)), "r"((uint32_t)(cnt)) : "memory")
#define MBAR_ARRIVE(addr) \
    asm volatile("mbarrier.arrive.shared.b64 _, [%0];" :: "r"((uint32_t)(addr)) : "memory")
#define MBAR_WAIT(addr, ph) do {                                                     \
    uint32_t _a = (uint32_t)(addr), _p = (uint32_t)(ph);                             \
    asm volatile("{\n\t.reg .pred P;\n\t"                                            \
        "WL%=:\n\t"                                                                  \
        "mbarrier.try_wait.parity.acquire.cta.shared::cta.b64 P, [%0], %1, 0x989680;\n\t" \
        "@P bra.uni WD%=;\n\t"                                                       \
        "bra.uni WL%=;\n\t"                                                          \
        "WD%=:\n\t}" :: "r"(_a), "r"(_p) : "memory");                                \
} while (0)
#define CP_MBAR_ARRIVE(addr) \
    asm volatile("cp.async.mbarrier.arrive.shared::cta.b64 [%0];" :: "r"((uint32_t)(addr)) : "memory")

// half2 {1.0 or 0.0, 1.0 or 0.0} from 2 mask bits (bit0 -> lo, bit1 -> hi)
__device__ __forceinline__ uint32_t pair_h2(uint32_t v2) {
    return ((v2 & 1u) * 0x3C00u) | ((v2 >> 1) * 0x3C000000u);
}

// ---------------- Kernel A: Yt = fp16(W @ X^T) per batch ----------------
#define A_SMEM_BYTES ((64 + 128) * 132 * 4)

__global__ __launch_bounds__(256, 2) void k_xw(const float* __restrict__ X,
                                               const float* __restrict__ W) {
    extern __shared__ float sm[];
    float* sX = sm;              // [64][132]   node rows
    float* sW = sm + 64 * 132;   // [128][132]  f rows
    const int tid = threadIdx.x;
    const long rbase = (long)blockIdx.x * 64;      // b*2048 + nbase
    const int b = (int)(rbase >> 11);
    const int nbase = (int)(rbase & 2047);

    uint32_t sXb = (uint32_t)__cvta_generic_to_shared(sX);
    uint32_t sWb = (uint32_t)__cvta_generic_to_shared(sW);

#pragma unroll
    for (int i = 0; i < 8; ++i) {
        int id = tid + i * 256;
        int r = id >> 5;
        int c4 = (id & 31) * 4;
        cpa16(sXb + (uint32_t)(r * 132 + c4) * 4, X + (rbase + r) * FF + c4);
    }
#pragma unroll
    for (int i = 0; i < 16; ++i) {
        int id = tid + i * 256;
        int r = id >> 5;
        int c4 = (id & 31) * 4;
        cpa16(sWb + (uint32_t)(r * 132 + c4) * 4, W + r * FF + c4);
    }
    cpa_commit();
    cpa_wait<0>();
    __syncthreads();

    const int lane = tid & 31, warp = tid >> 5;
    const int wm = warp >> 1, wn = warp & 1;
    const int gid = lane >> 2, tig = lane & 3;

    float acc[2][4][4];
#pragma unroll
    for (int mt = 0; mt < 2; ++mt)
#pragma unroll
        for (int nt = 0; nt < 4; ++nt)
#pragma unroll
            for (int j = 0; j < 4; ++j) acc[mt][nt][j] = 0.f;

#pragma unroll
    for (int ks = 0; ks < 16; ++ks) {
        const int k0 = ks * 8;
        uint32_t af[2][4];
#pragma unroll
        for (int mt = 0; mt < 2; ++mt) {          // A rows = f, from sW
            int f = wm * 32 + mt * 16 + gid;
            af[mt][0] = f2tf32(sW[f * 132 + k0 + tig]);
            af[mt][1] = f2tf32(sW[(f + 8) * 132 + k0 + tig]);
            af[mt][2] = f2tf32(sW[f * 132 + k0 + tig + 4]);
            af[mt][3] = f2tf32(sW[(f + 8) * 132 + k0 + tig + 4]);
        }
        uint32_t bf[4][2];
#pragma unroll
        for (int nt = 0; nt < 4; ++nt) {          // B rows = nodes, from sX
            int n = wn * 32 + nt * 8 + gid;
            bf[nt][0] = f2tf32(sX[n * 132 + k0 + tig]);
            bf[nt][1] = f2tf32(sX[n * 132 + k0 + tig + 4]);
        }
#pragma unroll
        for (int mt = 0; mt < 2; ++mt)
#pragma unroll
            for (int nt = 0; nt < 4; ++nt)
                mma_tf32(acc[mt][nt], af[mt], bf[nt], acc[mt][nt]);
    }

    // store Yt[b][f][node] as fp16 (half2 per thread: adjacent nodes)
    __half* Ybase = g_Yt + (long)b * FF * NN;
#pragma unroll
    for (int mt = 0; mt < 2; ++mt)
#pragma unroll
        for (int h = 0; h < 2; ++h) {
            int f = wm * 32 + mt * 16 + gid + 8 * h;
#pragma unroll
            for (int nt = 0; nt < 4; ++nt) {
                int n0 = wn * 32 + nt * 8 + 2 * tig;
                __half2 hv = __floats2half2_rn(acc[mt][nt][2 * h + 0],
                                               acc[mt][nt][2 * h + 1]);
                *(__half2*)&Ybase[(long)f * NN + nbase + n0] = hv;
            }
        }
}

// ---------------- Kernel B: fp16 warp-specialized pipelined masked GEMM ----------------
// 256 threads: warps 0-3 consumers (each M=64 x N=32), warps 4-7 producers.
// Producer warp pw owns edge-rows pw*16..pw*16+15: its own ballots ARE the masks
// it needs for A-frag expansion (register-resident + shfl) -> no cross-warp
// barrier, no mask STS/LDS. Per-row counts accumulate in producer registers and
// are written to smem once at the end (DONE mbarrier hands them to consumers).
#define KC 64
#define Y_ROW 144
#define STG_Y (128 * Y_ROW)                  // 18432
#define STG_A 8192
#define OFF_Y 0
#define OFF_A (4 * STG_Y)                    // 73728
#define OFF_CNT (OFF_A + 4 * STG_A)          // 106496 (64 x 4B)
#define OFF_FULL (OFF_CNT + 256)             // 106752
#define OFF_EMPTY (OFF_FULL + 32)            // 106784
#define OFF_DONE (OFF_EMPTY + 32)            // 106816
#define B_SMEM_BYTES (OFF_DONE + 16)         // 106832

__global__ __launch_bounds__(256, 2) void k_agg(const float* __restrict__ adj,
                                                const float* __restrict__ bias,
                                                float* __restrict__ out) {
    extern __shared__ char smc[];
    const uint32_t sb = smem_u32(smc);
    const int tid = threadIdx.x, wid = tid >> 5, lane = tid & 31;
    const int eb = blockIdx.x * 64, b = blockIdx.y;
    const float* adjBase = adj + ((long)b * EE + eb) * NN;
    const __half* Ytb = g_Yt + (long)b * FF * NN;

    if (tid == 0) {
#pragma unroll
        for (int i = 0; i < 4; ++i) {
            MBAR_INIT(sb + OFF_FULL + i * 8, 4);     // 4 producer warp leaders (+cp self-balance)
            MBAR_INIT(sb + OFF_EMPTY + i * 8, 4);    // 4 consumer warp leaders
        }
        MBAR_INIT(sb + OFF_DONE, 4);                 // 4 producer warp leaders
    }
    __syncthreads();

    if (wid >= 4) {
        // ===================== producer =====================
        const int p = tid - 128;            // 0..127
        const int pw = p >> 5, pl = p & 31; // warp pw owns rows pw*16..+15
        const int egid = pl >> 2, etig = pl & 3;

        const float* arow = adjBase + (long)(pw * 16) * NN + pl;
        float v0[16], v1[16], vn0[16], vn1[16];
#pragma unroll
        for (int i = 0; i < 16; ++i) {      // chunk 0
            v0[i] = arow[(long)i * NN];
            v1[i] = arow[(long)i * NN + 32];
        }
        int cnt = 0;                        // lane i<16: count for row pw*16+i

#pragma unroll 1
        for (int s = 0; s < NN / KC; ++s) {
            const int slot = s & 3;
            MBAR_WAIT(sb + OFF_EMPTY + slot * 8, ((s >> 2) & 1) ^ 1);

            // Y tile via cp.async: thread p owns f-row p (128 B)
            {
                const char* ysrc = (const char*)(Ytb + (long)p * NN + s * KC);
                uint32_t ydst = sb + OFF_Y + slot * STG_Y + (uint32_t)p * Y_ROW;
#pragma unroll
                for (int j = 0; j < 8; ++j)
                    cpa16(ydst + j * 16, ysrc + j * 16);
            }
            CP_MBAR_ARRIVE(sb + OFF_FULL + slot * 8);

            // prefetch next adj chunk
            if (s + 1 < NN / KC) {
                const float* an = arow + (s + 1) * KC;
#pragma unroll
                for (int i = 0; i < 16; ++i) {
                    vn0[i] = an[(long)i * NN];
                    vn1[i] = an[(long)i * NN + 32];
                }
            }

            // ballots; lane i keeps row i's two words in registers
            uint32_t mk0 = 0, mk1 = 0;
#pragma unroll
            for (int i = 0; i < 16; ++i) {
                uint32_t m0 = __ballot_sync(0xffffffffu, v0[i] == -1.f);
                uint32_t m1 = __ballot_sync(0xffffffffu, v1[i] == -1.f);
                if (pl == i) { mk0 = m0; mk1 = m1; }
            }
            cnt += __popc(mk0) + __popc(mk1);    // valid for lanes < 16

            // expansion rows: r0 = pw*16+egid, r0+8 -> lanes egid, egid+8
            uint32_t r0h0 = __shfl_sync(0xffffffffu, mk0, egid);
            uint32_t r0h1 = __shfl_sync(0xffffffffu, mk1, egid);
            uint32_t r1h0 = __shfl_sync(0xffffffffu, mk0, egid + 8);
            uint32_t r1h1 = __shfl_sync(0xffffffffu, mk1, egid + 8);

            uint32_t abase = sb + OFF_A + slot * STG_A + (uint32_t)(pw * 32 + pl) * 16;
#pragma unroll
            for (int t = 0; t < 4; ++t) {
                uint32_t w0 = (t < 2) ? r0h0 : r0h1;
                uint32_t w1 = (t < 2) ? r1h0 : r1h1;
                int sh = (t & 1) * 16 + 2 * etig;
                uint32_t a0 = pair_h2((w0 >> sh) & 3u);
                uint32_t a1 = pair_h2((w1 >> sh) & 3u);
                uint32_t a2 = pair_h2((w0 >> (sh + 8)) & 3u);
                uint32_t a3 = pair_h2((w1 >> (sh + 8)) & 3u);
                asm volatile("st.shared.v4.b32 [%0], {%1,%2,%3,%4};"
                             :: "r"(abase + (uint32_t)t * 2048),
                                "r"(a0), "r"(a1), "r"(a2), "r"(a3));
            }
            __syncwarp();
            if (pl == 0) MBAR_ARRIVE(sb + OFF_FULL + slot * 8);

#pragma unroll
            for (int i = 0; i < 16; ++i) {
                v0[i] = vn0[i];
                v1[i] = vn1[i];
            }
        }

        // publish per-row counts once
        if (pl < 16) ((int*)(smc + OFF_CNT))[pw * 16 + pl] = cnt;
        __syncwarp();
        if (pl == 0) MBAR_ARRIVE(sb + OFF_DONE);
    } else {
        // ===================== consumer =====================
        const int wn = wid;                       // f block: wn*32 .. wn*32+31
        const int gid = lane >> 2, tig = lane & 3;

        float acc[4][4][4];
#pragma unroll
        for (int mt = 0; mt < 4; ++mt)
#pragma unroll
            for (int nt = 0; nt < 4; ++nt)
#pragma unroll
                for (int j = 0; j < 4; ++j) acc[mt][nt][j] = 0.f;

        const uint32_t lm1 = (uint32_t)((wn * 32 + ((lane >> 4) & 1) * 8 + (lane & 7)) * Y_ROW +
                                        ((lane >> 3) & 1) * 16);
        const uint32_t lm2 = lm1 + 16 * Y_ROW;
        const uint32_t aoff = (uint32_t)lane * 16;

#pragma unroll 1
        for (int s = 0; s < NN / KC; ++s) {
            const int slot = s & 3;
            MBAR_WAIT(sb + OFF_FULL + slot * 8, (s >> 2) & 1);

            const uint32_t yb = sb + OFF_Y + slot * STG_Y;
            const uint32_t ab = sb + OFF_A + slot * STG_A;
#pragma unroll
            for (int t = 0; t < 4; ++t) {
                uint32_t a[4][4];
#pragma unroll
                for (int mt = 0; mt < 4; ++mt)
                    asm volatile("ld.shared.v4.b32 {%0,%1,%2,%3}, [%4];"
                                 : "=r"(a[mt][0]), "=r"(a[mt][1]),
                                   "=r"(a[mt][2]), "=r"(a[mt][3])
                                 : "r"(ab + (uint32_t)t * 2048 + (uint32_t)mt * 512 + aoff));
                uint32_t b01[4], b23[4];
                ldsm_x4(b01[0], b01[1], b01[2], b01[3], yb + (uint32_t)t * 32 + lm1);
                ldsm_x4(b23[0], b23[1], b23[2], b23[3], yb + (uint32_t)t * 32 + lm2);
#pragma unroll
                for (int mt = 0; mt < 4; ++mt) {
                    mma_f16(acc[mt][0], a[mt], b01[0], b01[1], acc[mt][0]);
                    mma_f16(acc[mt][1], a[mt], b01[2], b01[3], acc[mt][1]);
                    mma_f16(acc[mt][2], a[mt], b23[0], b23[1], acc[mt][2]);
                    mma_f16(acc[mt][3], a[mt], b23[2], b23[3], acc[mt][3]);
                }
            }
            __syncwarp();
            if (lane == 0) MBAR_ARRIVE(sb + OFF_EMPTY + slot * 8);
        }

        // wait for producer-published counts
        MBAR_WAIT(sb + OFF_DONE, 0);

        // epilogue: row r = mt*16 + gid + 8h
        const int* sCnt = (const int*)(smc + OFF_CNT);
#pragma unroll
        for (int mt = 0; mt < 4; ++mt)
#pragma unroll
            for (int h = 0; h < 2; ++h) {
                int r = mt * 16 + gid + 8 * h;
                float c = (float)sCnt[r];
                float inv = (c > 0.f) ? (1.f / c) : 1.f;
#pragma unroll
                for (int nt = 0; nt < 4; ++nt) {
                    int cidx = wn * 32 + nt * 8 + 2 * tig;
                    float2 bv = *(const float2*)&bias[cidx];
                    float v0 = fmaxf(acc[mt][nt][2 * h + 0] * inv + bv.x, 0.f);
                    float v1 = fmaxf(acc[mt][nt][2 * h + 1] * inv + bv.y, 0.f);
                    *(float2*)&out[((long)b * EE + eb + r) * FF + cidx] =
                        make_float2(v0, v1);
                }
            }
    }
}

// ---------------- launch ----------------
extern "C" void kernel_launch(void* const* d_in, const int* in_sizes, int n_in,
                              void* d_out, int out_size) {
    const float* X = (const float*)d_in[0];     // node_embeddings [B,N,F]
    const float* adj = (const float*)d_in[1];   // adj [B,E,N]
    const float* W = (const float*)d_in[2];     // W [F,F]
    const float* bias = (const float*)d_in[3];  // b [F]
    float* out = (float*)d_out;

    cudaFuncSetAttribute(k_xw, cudaFuncAttributeMaxDynamicSharedMemorySize, A_SMEM_BYTES);
    cudaFuncSetAttribute(k_agg, cudaFuncAttributeMaxDynamicSharedMemorySize, B_SMEM_BYTES);

    k_xw<<<(BB * NN) / 64, 256, A_SMEM_BYTES>>>(X, W);
    k_agg<<<dim3(EE / 64, BB), 256, B_SMEM_BYTES>>>(adj, bias, out);
}

// round 15
// speedup vs baseline: 1.3009x; 1.0856x over previous
#include <cuda_runtime.h>
#include <cuda_fp16.h>
#include <cstdint>

#define BB 8
#define EE 2048
#define NN 2048
#define FF 128

// Y^T scratch: [b][f][node], fp16 (4 MiB). node contiguous -> B-fragment K-pairs.
__device__ __half g_Yt[BB * FF * NN];

// ---------------- helpers ----------------
__device__ __forceinline__ uint32_t smem_u32(const void* p) {
    uint32_t a;
    asm("{ .reg .u64 t; cvta.to.shared.u64 t, %1; cvt.u32.u64 %0, t; }"
        : "=r"(a) : "l"(p));
    return a;
}
__device__ __forceinline__ uint32_t f2tf32(float x) {
    uint32_t r;
    asm("cvt.rna.tf32.f32 %0, %1;" : "=r"(r) : "f"(x));
    return r;
}
__device__ __forceinline__ void mma_tf32(float d[4], const uint32_t a[4],
                                         const uint32_t b[2], const float c[4]) {
    asm volatile(
        "mma.sync.aligned.m16n8k8.row.col.f32.tf32.tf32.f32 "
        "{%0,%1,%2,%3}, {%4,%5,%6,%7}, {%8,%9}, {%10,%11,%12,%13};"
        : "=f"(d[0]), "=f"(d[1]), "=f"(d[2]), "=f"(d[3])
        : "r"(a[0]), "r"(a[1]), "r"(a[2]), "r"(a[3]),
          "r"(b[0]), "r"(b[1]),
          "f"(c[0]), "f"(c[1]), "f"(c[2]), "f"(c[3]));
}
__device__ __forceinline__ void mma_f16(float d[4], const uint32_t a[4],
                                        const uint32_t b0, const uint32_t b1,
                                        const float c[4]) {
    asm volatile(
        "mma.sync.aligned.m16n8k16.row.col.f32.f16.f16.f32 "
        "{%0,%1,%2,%3}, {%4,%5,%6,%7}, {%8,%9}, {%10,%11,%12,%13};"
        : "=f"(d[0]), "=f"(d[1]), "=f"(d[2]), "=f"(d[3])
        : "r"(a[0]), "r"(a[1]), "r"(a[2]), "r"(a[3]),
          "r"(b0), "r"(b1),
          "f"(c[0]), "f"(c[1]), "f"(c[2]), "f"(c[3]));
}
__device__ __forceinline__ void ldsm_x4(uint32_t& d0, uint32_t& d1,
                                        uint32_t& d2, uint32_t& d3, uint32_t addr) {
    asm volatile("ldmatrix.sync.aligned.m8n8.x4.shared.b16 {%0,%1,%2,%3}, [%4];"
                 : "=r"(d0), "=r"(d1), "=r"(d2), "=r"(d3) : "r"(addr));
}
__device__ __forceinline__ void cpa16(uint32_t s, const void* g) {
    asm volatile("cp.async.cg.shared.global [%0], [%1], 16;" :: "r"(s), "l"(g));
}
__device__ __forceinline__ void cpa_commit() { asm volatile("cp.async.commit_group;"); }
template <int W> __device__ __forceinline__ void cpa_wait() {
    asm volatile("cp.async.wait_group %0;" :: "n"(W));
}

#define MBAR_INIT(addr, cnt) \
    asm volatile("mbarrier.init.shared.b64 [%0], %1;" :: "r"((uint32_t)(addr)), "r"((uint32_t)(cnt)) : "memory")
#define MBAR_ARRIVE(addr) \
    asm volatile("mbarrier.arrive.shared.b64 _, [%0];" :: "r"((uint32_t)(addr)) : "memory")
#define MBAR_WAIT(addr, ph) do {                                                     \
    uint32_t _a = (uint32_t)(addr), _p = (uint32_t)(ph);                             \
    asm volatile("{\n\t.reg .pred P;\n\t"                                            \
        "WL%=:\n\t"                                                                  \
        "mbarrier.try_wait.parity.acquire.cta.shared::cta.b64 P, [%0], %1, 0x989680;\n\t" \
        "@P bra.uni WD%=;\n\t"                                                       \
        "bra.uni WL%=;\n\t"                                                          \
        "WD%=:\n\t}" :: "r"(_a), "r"(_p) : "memory");                                \
} while (0)
#define CP_MBAR_ARRIVE(addr) \
    asm volatile("cp.async.mbarrier.arrive.shared::cta.b64 [%0];" :: "r"((uint32_t)(addr)) : "memory")

// half2 {1.0 or 0.0, 1.0 or 0.0} from 2 mask bits (bit0 -> lo, bit1 -> hi)
__device__ __forceinline__ uint32_t pair_h2(uint32_t v2) {
    return ((v2 & 1u) * 0x3C00u) | ((v2 >> 1) * 0x3C000000u);
}

// ---------------- Kernel A: Yt = fp16(W @ X^T) per batch ----------------
#define A_SMEM_BYTES ((64 + 128) * 132 * 4)

__global__ __launch_bounds__(256, 2) void k_xw(const float* __restrict__ X,
                                               const float* __restrict__ W) {
    extern __shared__ float sm[];
    float* sX = sm;              // [64][132]   node rows
    float* sW = sm + 64 * 132;   // [128][132]  f rows
    const int tid = threadIdx.x;
    const long rbase = (long)blockIdx.x * 64;      // b*2048 + nbase
    const int b = (int)(rbase >> 11);
    const int nbase = (int)(rbase & 2047);

    uint32_t sXb = (uint32_t)__cvta_generic_to_shared(sX);
    uint32_t sWb = (uint32_t)__cvta_generic_to_shared(sW);

#pragma unroll
    for (int i = 0; i < 8; ++i) {
        int id = tid + i * 256;
        int r = id >> 5;
        int c4 = (id & 31) * 4;
        cpa16(sXb + (uint32_t)(r * 132 + c4) * 4, X + (rbase + r) * FF + c4);
    }
#pragma unroll
    for (int i = 0; i < 16; ++i) {
        int id = tid + i * 256;
        int r = id >> 5;
        int c4 = (id & 31) * 4;
        cpa16(sWb + (uint32_t)(r * 132 + c4) * 4, W + r * FF + c4);
    }
    cpa_commit();
    cpa_wait<0>();
    __syncthreads();

    const int lane = tid & 31, warp = tid >> 5;
    const int wm = warp >> 1, wn = warp & 1;
    const int gid = lane >> 2, tig = lane & 3;

    float acc[2][4][4];
#pragma unroll
    for (int mt = 0; mt < 2; ++mt)
#pragma unroll
        for (int nt = 0; nt < 4; ++nt)
#pragma unroll
            for (int j = 0; j < 4; ++j) acc[mt][nt][j] = 0.f;

#pragma unroll
    for (int ks = 0; ks < 16; ++ks) {
        const int k0 = ks * 8;
        uint32_t af[2][4];
#pragma unroll
        for (int mt = 0; mt < 2; ++mt) {          // A rows = f, from sW
            int f = wm * 32 + mt * 16 + gid;
            af[mt][0] = f2tf32(sW[f * 132 + k0 + tig]);
            af[mt][1] = f2tf32(sW[(f + 8) * 132 + k0 + tig]);
            af[mt][2] = f2tf32(sW[f * 132 + k0 + tig + 4]);
            af[mt][3] = f2tf32(sW[(f + 8) * 132 + k0 + tig + 4]);
        }
        uint32_t bf[4][2];
#pragma unroll
        for (int nt = 0; nt < 4; ++nt) {          // B rows = nodes, from sX
            int n = wn * 32 + nt * 8 + gid;
            bf[nt][0] = f2tf32(sX[n * 132 + k0 + tig]);
            bf[nt][1] = f2tf32(sX[n * 132 + k0 + tig + 4]);
        }
#pragma unroll
        for (int mt = 0; mt < 2; ++mt)
#pragma unroll
            for (int nt = 0; nt < 4; ++nt)
                mma_tf32(acc[mt][nt], af[mt], bf[nt], acc[mt][nt]);
    }

    // store Yt[b][f][node] as fp16 (half2 per thread: adjacent nodes)
    __half* Ybase = g_Yt + (long)b * FF * NN;
#pragma unroll
    for (int mt = 0; mt < 2; ++mt)
#pragma unroll
        for (int h = 0; h < 2; ++h) {
            int f = wm * 32 + mt * 16 + gid + 8 * h;
#pragma unroll
            for (int nt = 0; nt < 4; ++nt) {
                int n0 = wn * 32 + nt * 8 + 2 * tig;
                __half2 hv = __floats2half2_rn(acc[mt][nt][2 * h + 0],
                                               acc[mt][nt][2 * h + 1]);
                *(__half2*)&Ybase[(long)f * NN + nbase + n0] = hv;
            }
        }
}

// ---------------- Kernel B: fp16 warp-specialized pipelined masked GEMM ----------------
// 384 threads: warps 0-7 consumers (2x4 grid: M=32, N=32 each; acc=32 regs),
//              warps 8-11 producers (Y cp.async + adj ballots -> mask words only).
// 5-stage ring: Y fp16 [128 f][64 nodes] rows padded 144B + 64x2 mask words.
// Consumers expand their own A-frags from mask words (R13-proven mapping) --
// no A smem tile, no producer expansion, no cross-producer barrier.
#define KC 64
#define Y_ROW 144
#define NSTG 5
#define STG_Y (128 * Y_ROW)                  // 18432
#define OFF_Y 0
#define OFF_MASK (NSTG * STG_Y)              // 92160  (NSTG x 64 x 8B)
#define OFF_CNT (OFF_MASK + NSTG * 512)      // 94720  (64 x 4B)
#define OFF_FULL (OFF_CNT + 256)             // 94976  (NSTG x 8B)
#define OFF_EMPTY (OFF_FULL + NSTG * 8)      // 95016
#define OFF_DONE (OFF_EMPTY + NSTG * 8)      // 95056
#define B_SMEM_BYTES (OFF_DONE + 8)          // 95064

__global__ __launch_bounds__(384, 2) void k_agg(const float* __restrict__ adj,
                                                const float* __restrict__ bias,
                                                float* __restrict__ out) {
    extern __shared__ char smc[];
    const uint32_t sb = smem_u32(smc);
    const int tid = threadIdx.x, wid = tid >> 5, lane = tid & 31;
    const int eb = blockIdx.x * 64, b = blockIdx.y;
    const float* adjBase = adj + ((long)b * EE + eb) * NN;
    const __half* Ytb = g_Yt + (long)b * FF * NN;

    if (tid == 0) {
#pragma unroll
        for (int i = 0; i < NSTG; ++i) {
            MBAR_INIT(sb + OFF_FULL + i * 8, 4);     // 4 producer leaders (+cp self-balance)
            MBAR_INIT(sb + OFF_EMPTY + i * 8, 8);    // 8 consumer leaders
        }
        MBAR_INIT(sb + OFF_DONE, 4);
    }
    __syncthreads();

    if (wid >= 8) {
        // ===================== producer =====================
        const int p = tid - 256;            // 0..127
        const int pw = p >> 5, pl = p & 31; // warp pw owns edge rows pw*16..+15
        const float* arow = adjBase + (long)(pw * 16) * NN + pl;
        int cnt = 0;                        // lane i<16: count for row pw*16+i
        int slot = 0, ph = 1;               // producer starts phase-flipped

#pragma unroll 1
        for (int s = 0; s < NN / KC; ++s) {
            MBAR_WAIT(sb + OFF_EMPTY + slot * 8, ph);

            // Y tile via cp.async: thread p owns f-row p (128 B)
            {
                const char* ysrc = (const char*)(Ytb + (long)p * NN + s * KC);
                uint32_t ydst = sb + OFF_Y + slot * STG_Y + (uint32_t)p * Y_ROW;
#pragma unroll
                for (int j = 0; j < 8; ++j)
                    cpa16(ydst + j * 16, ysrc + j * 16);
            }
            CP_MBAR_ARRIVE(sb + OFF_FULL + slot * 8);

            // adj chunk: issue all 32 loads (MLP), then ballots
            float v0[16], v1[16];
            const float* ac = arow + s * KC;
#pragma unroll
            for (int i = 0; i < 16; ++i) {
                v0[i] = ac[(long)i * NN];
                v1[i] = ac[(long)i * NN + 32];
            }
            uint32_t mk0 = 0, mk1 = 0;
#pragma unroll
            for (int i = 0; i < 16; ++i) {
                uint32_t m0 = __ballot_sync(0xffffffffu, v0[i] == -1.f);
                uint32_t m1 = __ballot_sync(0xffffffffu, v1[i] == -1.f);
                if (pl == i) { mk0 = m0; mk1 = m1; }
            }
            cnt += __popc(mk0) + __popc(mk1);
            if (pl < 16)
                asm volatile("st.shared.v2.b32 [%0], {%1,%2};"
                             :: "r"(sb + OFF_MASK + (uint32_t)(slot * 512 + (pw * 16 + pl) * 8)),
                                "r"(mk0), "r"(mk1));
            __syncwarp();
            if (pl == 0) MBAR_ARRIVE(sb + OFF_FULL + slot * 8);

            if (++slot == NSTG) { slot = 0; ph ^= 1; }
        }

        // publish per-row counts once
        if (pl < 16) ((int*)(smc + OFF_CNT))[pw * 16 + pl] = cnt;
        __syncwarp();
        if (pl == 0) MBAR_ARRIVE(sb + OFF_DONE);
    } else {
        // ===================== consumer =====================
        const int wm = wid & 1, wn = wid >> 1;    // M-half, N-block
        const int gid = lane >> 2, tig = lane & 3;

        float acc[2][4][4];
#pragma unroll
        for (int mt = 0; mt < 2; ++mt)
#pragma unroll
            for (int nt = 0; nt < 4; ++nt)
#pragma unroll
                for (int j = 0; j < 4; ++j) acc[mt][nt][j] = 0.f;

        const uint32_t lm1 = (uint32_t)((wn * 32 + ((lane >> 4) & 1) * 8 + (lane & 7)) * Y_ROW +
                                        ((lane >> 3) & 1) * 16);
        const uint32_t lm2 = lm1 + 16 * Y_ROW;
        int slot = 0, ph = 0;

#pragma unroll 1
        for (int s = 0; s < NN / KC; ++s) {
            MBAR_WAIT(sb + OFF_FULL + slot * 8, ph);

            // masks for my 4 rows (wm*32 + gid + 8j)
            uint32_t rw0[4], rw1[4];
#pragma unroll
            for (int j = 0; j < 4; ++j)
                asm volatile("ld.shared.v2.b32 {%0,%1}, [%2];"
                             : "=r"(rw0[j]), "=r"(rw1[j])
                             : "r"(sb + OFF_MASK +
                                   (uint32_t)(slot * 512 + (wm * 32 + gid + 8 * j) * 8)));

            const uint32_t yb = sb + OFF_Y + slot * STG_Y;
#pragma unroll
            for (int t = 0; t < 4; ++t) {
                uint32_t b01[4], b23[4];
                ldsm_x4(b01[0], b01[1], b01[2], b01[3], yb + (uint32_t)t * 32 + lm1);
                ldsm_x4(b23[0], b23[1], b23[2], b23[3], yb + (uint32_t)t * 32 + lm2);
                const int sh = (t & 1) * 16 + 2 * tig;
#pragma unroll
                for (int mt = 0; mt < 2; ++mt) {
                    uint32_t w0 = (t < 2) ? rw0[2 * mt] : rw1[2 * mt];
                    uint32_t w1 = (t < 2) ? rw0[2 * mt + 1] : rw1[2 * mt + 1];
                    uint32_t a[4];
                    a[0] = pair_h2((w0 >> sh) & 3u);
                    a[1] = pair_h2((w1 >> sh) & 3u);
                    a[2] = pair_h2((w0 >> (sh + 8)) & 3u);
                    a[3] = pair_h2((w1 >> (sh + 8)) & 3u);
                    mma_f16(acc[mt][0], a, b01[0], b01[1], acc[mt][0]);
                    mma_f16(acc[mt][1], a, b01[2], b01[3], acc[mt][1]);
                    mma_f16(acc[mt][2], a, b23[0], b23[1], acc[mt][2]);
                    mma_f16(acc[mt][3], a, b23[2], b23[3], acc[mt][3]);
                }
            }
            __syncwarp();
            if (lane == 0) MBAR_ARRIVE(sb + OFF_EMPTY + slot * 8);

            if (++slot == NSTG) { slot = 0; ph ^= 1; }
        }

        // wait for producer-published counts
        MBAR_WAIT(sb + OFF_DONE, 0);

        // epilogue: row r = wm*32 + mt*16 + gid + 8h
        const int* sCnt = (const int*)(smc + OFF_CNT);
#pragma unroll
        for (int mt = 0; mt < 2; ++mt)
#pragma unroll
            for (int h = 0; h < 2; ++h) {
                int r = wm * 32 + mt * 16 + gid + 8 * h;
                float c = (float)sCnt[r];
                float inv = (c > 0.f) ? (1.f / c) : 1.f;
#pragma unroll
                for (int nt = 0; nt < 4; ++nt) {
                    int cidx = wn * 32 + nt * 8 + 2 * tig;
                    float2 bv = *(const float2*)&bias[cidx];
                    float v0 = fmaxf(acc[mt][nt][2 * h + 0] * inv + bv.x, 0.f);
                    float v1 = fmaxf(acc[mt][nt][2 * h + 1] * inv + bv.y, 0.f);
                    *(float2*)&out[((long)b * EE + eb + r) * FF + cidx] =
                        make_float2(v0, v1);
                }
            }
    }
}

// ---------------- launch ----------------
extern "C" void kernel_launch(void* const* d_in, const int* in_sizes, int n_in,
                              void* d_out, int out_size) {
    const float* X = (const float*)d_in[0];     // node_embeddings [B,N,F]
    const float* adj = (const float*)d_in[1];   // adj [B,E,N]
    const float* W = (const float*)d_in[2];     // W [F,F]
    const float* bias = (const float*)d_in[3];  // b [F]
    float* out = (float*)d_out;

    cudaFuncSetAttribute(k_xw, cudaFuncAttributeMaxDynamicSharedMemorySize, A_SMEM_BYTES);
    cudaFuncSetAttribute(k_agg, cudaFuncAttributeMaxDynamicSharedMemorySize, B_SMEM_BYTES);

    k_xw<<<(BB * NN) / 64, 256, A_SMEM_BYTES>>>(X, W);
    k_agg<<<dim3(EE / 64, BB), 384, B_SMEM_BYTES>>>(adj, bias, out);
}